// round 16
// baseline (speedup 1.0000x reference)
#include <cuda_runtime.h>
#include <math.h>
#include <stdint.h>

#define NODES 1024
#define FDIM  64
#define HID   32
#define HH    16
#define EDGES 65536
#define BI    32     // i-rows per dense CTA
#define BJ    128    // j-cols per dense CTA (8 warps x 16)

#define DENSE_BLOCKS 256
#define EDGE_BLOCKS  32
#define EDGES_PER_BLOCK 2048   // 8 reps of 256

// Precomputed per-node terms: A = x @ W1[0:64] + b1 ; B = x @ W1[64:128]
__device__ float g_A[NODES * HID];
__device__ float g_B[NODES * HID];

// ======================= prep: per-node A/B =======================
__global__ void prep_kernel(const float* __restrict__ x,
                            const float* __restrict__ W1,
                            const float* __restrict__ b1) {
    __shared__ float xr[4][FDIM];
    int t = threadIdx.x;                     // 256
    int nl = t >> 6, s = t & 63;
    int node = blockIdx.x * 4 + nl;
    xr[nl][s] = x[node * FDIM + s];
    __syncthreads();
    int h = s & 31;
    const float* W = W1 + ((s < 32) ? 0 : FDIM * HID);
    float acc = (s < 32) ? b1[h] : 0.0f;
#pragma unroll
    for (int f = 0; f < FDIM; f++)
        acc = fmaf(xr[nl][f], W[f * HID + h], acc);
    if (s < 32) g_A[node * HID + h] = acc;
    else        g_B[node * HID + h] = acc;
}

// ======================= shared helpers =======================
// smem u32 layout (dense role):
//   sW    [8][32][8]        = 2048 u32
//   sXJ16 [128][34] (pad)   = 4352 u32
//   sXI16 [32][34]  (pad)   = 1088 u32
//   sA    [32][32] f32      = 1024 u32
#define SW_OFF   0
#define SXJ_OFF  2048
#define SXI_OFF  (2048 + 4352)
#define SA_OFF   (2048 + 4352 + 1088)
#define DENSE_SMEM_U (2048 + 4352 + 1088 + 1024)
#define XJP 34
#define XIP 34

__device__ __forceinline__ uint32_t pack_h2(float lo, float hi) {
    uint32_t r;
    asm("cvt.rn.f16x2.f32 %0, %1, %2;" : "=r"(r) : "f"(hi), "f"(lo));
    return r;
}
__device__ __forceinline__ uint32_t hsub2(uint32_t a, uint32_t b) {
    uint32_t r;
    asm("sub.f16x2 %0, %1, %2;" : "=r"(r) : "r"(a), "r"(b));
    return r;
}
__device__ __forceinline__ uint32_t habs2(uint32_t a) {
    return a & 0x7FFF7FFFu;
}
__device__ __forceinline__ uint32_t hmul2(uint32_t a, uint32_t b) {
    uint32_t r;
    asm("mul.f16x2 %0, %1, %2;" : "=r"(r) : "r"(a), "r"(b));
    return r;
}
__device__ __forceinline__ void mma_f16(float* D, uint32_t a0, uint32_t a1,
                                        uint32_t a2, uint32_t a3,
                                        uint32_t b0, uint32_t b1) {
    asm volatile(
        "mma.sync.aligned.m16n8k16.row.col.f32.f16.f16.f32 "
        "{%0,%1,%2,%3}, {%4,%5,%6,%7}, {%8,%9}, {%0,%1,%2,%3};"
        : "+f"(D[0]), "+f"(D[1]), "+f"(D[2]), "+f"(D[3])
        : "r"(a0), "r"(a1), "r"(a2), "r"(a3), "r"(b0), "r"(b1));
}

// fast sigmoid (MUFU) for dense P -- tolerance-safe
__device__ __forceinline__ float sigmoid_fast(float v) {
    return __fdividef(1.0f, 1.0f + __expf(-v));
}

__device__ __forceinline__ unsigned long long pack2(float lo, float hi) {
    unsigned long long r;
    asm("mov.b64 %0, {%1, %2};" : "=l"(r) : "f"(lo), "f"(hi));
    return r;
}
__device__ __forceinline__ void unpack2(unsigned long long v, float& lo, float& hi) {
    asm("mov.b64 {%0, %1}, %2;" : "=f"(lo), "=f"(hi) : "l"(v));
}
__device__ __forceinline__ unsigned long long ffma2(unsigned long long a,
                                                    unsigned long long b,
                                                    unsigned long long c) {
    unsigned long long d;
    asm("fma.rn.f32x2 %0, %1, %2, %3;" : "=l"(d) : "l"(a), "l"(b), "l"(c));
    return d;
}

// ======================= dense role (identical math to R15) =======================
__device__ __forceinline__ void dense_role(uint32_t* smu, int bid,
                                           const float* __restrict__ x,
                                           const float* __restrict__ W1,
                                           const float* __restrict__ W2,
                                           const float* __restrict__ b2,
                                           float* __restrict__ P) {
    uint32_t* sW    = smu + SW_OFF;
    uint32_t* sXJ16 = smu + SXJ_OFF;
    uint32_t* sXI16 = smu + SXI_OFF;
    float*    sA    = (float*)(smu + SA_OFF);

    int t  = threadIdx.x;
    int i0 = (bid & 31) * BI;
    int j0 = (bid >> 5) * BJ;

    for (int k = t; k < BJ * 16; k += 256) {
        int row = k >> 4, c4 = k & 15;
        float4 v = __ldg((const float4*)(x + (j0 + row) * FDIM) + c4);
        sXJ16[row * XJP + c4 * 2]     = pack_h2(v.x, v.y);
        sXJ16[row * XJP + c4 * 2 + 1] = pack_h2(v.z, v.w);
    }
    for (int k = t; k < BI * 16; k += 256) {
        int row = k >> 4, c4 = k & 15;
        float4 v = __ldg((const float4*)(x + (i0 + row) * FDIM) + c4);
        sXI16[row * XIP + c4 * 2]     = pack_h2(v.x, v.y);
        sXI16[row * XIP + c4 * 2 + 1] = pack_h2(v.z, v.w);
    }
    for (int k = t; k < BI * HID; k += 256)
        sA[k] = g_A[(i0 + (k >> 5)) * HID + (k & 31)];
    for (int g = t; g < 8 * 32; g += 256) {
        int s = g >> 5, ln = g & 31;
        int qq = ln & 3, rr = ln >> 2;
        uint32_t* dst = sW + (s * 32 + ln) * 8;
        int kb = s * 16;
#pragma unroll
        for (int nt = 0; nt < 4; nt++) {
            int n = nt * 8 + rr;
            int f0 = kb + 2 * qq;
            int f2 = kb + 2 * qq + 8;
            float w00 = W1[(128 + f0) * HID + n];
            float w01 = W1[(128 + f0 + 1) * HID + n];
            float w20 = W1[(128 + f2) * HID + n];
            float w21 = W1[(128 + f2 + 1) * HID + n];
            dst[nt]     = pack_h2(w00, w01);
            dst[4 + nt] = pack_h2(w20, w21);
        }
    }
    __syncthreads();

    int lane = t & 31, wid = t >> 5;
    int q = lane & 3, r = lane >> 2;
    int jr0 = wid * 16 + r;
    int jr1 = jr0 + 8;

    uint32_t bf[8][8];
#pragma unroll
    for (int s = 0; s < 8; s++) {
        const uint32_t* bp = sW + (s * 32 + lane) * 8;
        float4 v0 = *(const float4*)bp;
        float4 v1 = *(const float4*)(bp + 4);
        bf[s][0] = __float_as_uint(v0.x); bf[s][1] = __float_as_uint(v0.y);
        bf[s][2] = __float_as_uint(v0.z); bf[s][3] = __float_as_uint(v0.w);
        bf[s][4] = __float_as_uint(v1.x); bf[s][5] = __float_as_uint(v1.y);
        bf[s][6] = __float_as_uint(v1.z); bf[s][7] = __float_as_uint(v1.w);
    }

    uint32_t xjA0[4], xjB0[4], xjA1[4], xjB1[4];
#pragma unroll
    for (int u = 0; u < 4; u++) {
        xjA0[u] = sXJ16[jr0 * XJP + u * 8 + q];
        xjB0[u] = sXJ16[jr0 * XJP + u * 8 + q + 4];
        xjA1[u] = sXJ16[jr1 * XJP + u * 8 + q];
        xjB1[u] = sXJ16[jr1 * XJP + u * 8 + q + 4];
    }

    float bj0[8], bj1[8], w2l[8];
#pragma unroll
    for (int nt = 0; nt < 4; nt++) {
        int h = nt * 8 + 2 * q;
        bj0[2 * nt]     = g_B[(j0 + jr0) * HID + h];
        bj0[2 * nt + 1] = g_B[(j0 + jr0) * HID + h + 1];
        bj1[2 * nt]     = g_B[(j0 + jr1) * HID + h];
        bj1[2 * nt + 1] = g_B[(j0 + jr1) * HID + h + 1];
        w2l[2 * nt]     = __ldg(W2 + h);
        w2l[2 * nt + 1] = __ldg(W2 + h + 1);
    }
    float b2v = __ldg(b2);

    for (int ii = 0; ii < BI; ii++) {
        uint32_t xiA[4], xiB[4];
#pragma unroll
        for (int u = 0; u < 4; u++) {
            xiA[u] = sXI16[ii * XIP + u * 8 + q];
            xiB[u] = sXI16[ii * XIP + u * 8 + q + 4];
        }

        float D[16];
#pragma unroll
        for (int z = 0; z < 16; z++) D[z] = 0.0f;

#pragma unroll
        for (int s = 0; s < 8; s++) {
            int u = s & 3;
            uint32_t a0, a1, a2, a3;
            if (s < 4) {
                a0 = habs2(hsub2(xiA[u], xjA0[u]));
                a1 = habs2(hsub2(xiA[u], xjA1[u]));
                a2 = habs2(hsub2(xiB[u], xjB0[u]));
                a3 = habs2(hsub2(xiB[u], xjB1[u]));
            } else {
                a0 = hmul2(xiA[u], xjA0[u]);
                a1 = hmul2(xiA[u], xjA1[u]);
                a2 = hmul2(xiB[u], xjB0[u]);
                a3 = hmul2(xiB[u], xjB1[u]);
            }
            mma_f16(D + 0,  a0, a1, a2, a3, bf[s][0], bf[s][4]);
            mma_f16(D + 4,  a0, a1, a2, a3, bf[s][1], bf[s][5]);
            mma_f16(D + 8,  a0, a1, a2, a3, bf[s][2], bf[s][6]);
            mma_f16(D + 12, a0, a1, a2, a3, bf[s][3], bf[s][7]);
        }

        float p0 = 0.0f, p1 = 0.0f;
#pragma unroll
        for (int nt = 0; nt < 4; nt++) {
            float2 aiv = *(const float2*)(sA + ii * HID + nt * 8 + 2 * q);
            p0 += fmaxf(D[nt * 4 + 0] + aiv.x + bj0[2 * nt],     0.0f) * w2l[2 * nt];
            p0 += fmaxf(D[nt * 4 + 1] + aiv.y + bj0[2 * nt + 1], 0.0f) * w2l[2 * nt + 1];
            p1 += fmaxf(D[nt * 4 + 2] + aiv.x + bj1[2 * nt],     0.0f) * w2l[2 * nt];
            p1 += fmaxf(D[nt * 4 + 3] + aiv.y + bj1[2 * nt + 1], 0.0f) * w2l[2 * nt + 1];
        }
        p0 += __shfl_xor_sync(0xFFFFFFFF, p0, 1);
        p0 += __shfl_xor_sync(0xFFFFFFFF, p0, 2);
        p1 += __shfl_xor_sync(0xFFFFFFFF, p1, 1);
        p1 += __shfl_xor_sync(0xFFFFFFFF, p1, 2);
        if (q == 0) {
            P[(i0 + ii) * NODES + j0 + jr0] = sigmoid_fast(p0 + b2v);
            P[(i0 + ii) * NODES + j0 + jr1] = sigmoid_fast(p1 + b2v);
        }
    }
}

// ======================= edge role (fp32 exact; sigmoid stays expf) =======================
__device__ __forceinline__ void edge_role(uint32_t* smu, int ebid,
                                          const float* __restrict__ x,
                                          const int* __restrict__ ei,
                                          const float* __restrict__ W1,
                                          const float* __restrict__ W2,
                                          const float* __restrict__ b2,
                                          float* __restrict__ probs,
                                          float* __restrict__ acts) {
    unsigned long long* s_Wc = (unsigned long long*)smu;   // [FDIM][HH]
    unsigned long long* s_Wd = s_Wc + FDIM * HH;           // [FDIM][HH]
    float* s_W2 = (float*)(s_Wd + FDIM * HH);              // [HID]

    int t = threadIdx.x;
    for (int k = t; k < FDIM * HH; k += 256) {
        int f = k >> 4, hh = k & 15;
        float2 c = ((const float2*)(W1 + (128 + f) * HID))[hh];
        float2 d = ((const float2*)(W1 + (192 + f) * HID))[hh];
        s_Wc[f * HH + hh] = pack2(c.x, c.y);
        s_Wd[f * HH + hh] = pack2(d.x, d.y);
    }
    if (t < HID) s_W2[t] = W2[t];
    __syncthreads();

    float b2v = b2[0];
    int e0 = ebid * EDGES_PER_BLOCK;

#pragma unroll 1
    for (int rep = 0; rep < EDGES_PER_BLOCK / 256; rep++) {
        int e = e0 + rep * 256 + t;
        int s = ei[e];
        int d = ei[EDGES + e];

        unsigned long long acc[HH];
        {
            const float* Ar = g_A + s * HID;
            const float* Br = g_B + d * HID;
#pragma unroll
            for (int hh = 0; hh < HH; hh++)
                acc[hh] = pack2(Ar[2 * hh] + Br[2 * hh], Ar[2 * hh + 1] + Br[2 * hh + 1]);
        }

        const float4* xs4 = (const float4*)(x + s * FDIM);
        const float4* xd4 = (const float4*)(x + d * FDIM);
#pragma unroll 4
        for (int c = 0; c < FDIM / 4; c++) {
            float4 a = __ldg(xs4 + c);
            float4 b = __ldg(xd4 + c);
            float av[4] = {a.x, a.y, a.z, a.w};
            float bv[4] = {b.x, b.y, b.z, b.w};
#pragma unroll
            for (int u = 0; u < 4; u++) {
                int f = c * 4 + u;
                float ad = fabsf(av[u] - bv[u]);
                float pr = av[u] * bv[u];
                unsigned long long dd = pack2(ad, ad);
                unsigned long long pm = pack2(pr, pr);
#pragma unroll
                for (int hh = 0; hh < HH; hh++) {
                    acc[hh] = ffma2(dd, s_Wc[f * HH + hh], acc[hh]);
                    acc[hh] = ffma2(pm, s_Wd[f * HH + hh], acc[hh]);
                }
            }
        }

        float logit = b2v;
#pragma unroll
        for (int hh = 0; hh < HH; hh++) {
            float lo, hi;
            unpack2(acc[hh], lo, hi);
            logit += fmaxf(lo, 0.0f) * s_W2[2 * hh] + fmaxf(hi, 0.0f) * s_W2[2 * hh + 1];
        }
        float prob = 1.0f / (1.0f + expf(-logit));   // exact path: acts threshold safety
        probs[e] = prob;
        acts[e]  = (prob > 0.4f) ? 1.0f : 0.0f;
    }
}

// ======================= fused kernel (one wave: 256 dense + 32 edge = 288 <= 296) =======================
__global__ __launch_bounds__(256, 2)
void fused_kernel(const float* __restrict__ x,
                  const int* __restrict__ ei,
                  const float* __restrict__ W1,
                  const float* __restrict__ W2,
                  const float* __restrict__ b2,
                  float* __restrict__ probs,
                  float* __restrict__ acts,
                  float* __restrict__ P) {
    extern __shared__ uint32_t smu[];
    int bid = blockIdx.x;
    if (bid < DENSE_BLOCKS) {
        dense_role(smu, bid, x, W1, W2, b2, P);
    } else {
        edge_role(smu, bid - DENSE_BLOCKS, x, ei, W1, W2, b2, probs, acts);
    }
}

// ======================= launch =======================
extern "C" void kernel_launch(void* const* d_in, const int* in_sizes, int n_in,
                              void* d_out, int out_size) {
    const float* x  = (const float*)d_in[0];
    const int*   ei = (const int*)d_in[1];     // int32 (JAX x64 disabled)
    const float* W1 = (const float*)d_in[3];
    const float* b1 = (const float*)d_in[4];
    const float* W2 = (const float*)d_in[5];
    const float* b2 = (const float*)d_in[6];

    float* out   = (float*)d_out;
    float* probs = out;
    float* acts  = out + EDGES;
    float* P     = out + 2 * EDGES;

    static int smem_set = 0;
    if (!smem_set) {
        cudaFuncSetAttribute(fused_kernel,
                             cudaFuncAttributeMaxDynamicSharedMemorySize,
                             DENSE_SMEM_U * 4);
        smem_set = 1;
    }

    prep_kernel<<<NODES / 4, 256>>>(x, W1, b1);
    fused_kernel<<<DENSE_BLOCKS + EDGE_BLOCKS, 256, DENSE_SMEM_U * 4>>>(
        x, ei, W1, W2, b2, probs, acts, P);
}

// round 17
// speedup vs baseline: 2.1429x; 2.1429x over previous
#include <cuda_runtime.h>
#include <math.h>
#include <stdint.h>

#define NODES 1024
#define FDIM  64
#define HID   32
#define HH    16
#define EDGES 65536
#define BI    32     // i-rows per dense CTA
#define BJ    128    // j-cols per dense CTA (8 warps x 16)

// Precomputed per-node terms: A = x @ W1[0:64] + b1 ; B = x @ W1[64:128]
__device__ float g_A[NODES * HID];
__device__ float g_B[NODES * HID];

// ======================= prep: per-node A/B =======================
__global__ void prep_kernel(const float* __restrict__ x,
                            const float* __restrict__ W1,
                            const float* __restrict__ b1) {
    __shared__ float xr[4][FDIM];
    int t = threadIdx.x;                     // 256
    int nl = t >> 6, s = t & 63;
    int node = blockIdx.x * 4 + nl;
    xr[nl][s] = x[node * FDIM + s];
    __syncthreads();
    int h = s & 31;
    const float* W = W1 + ((s < 32) ? 0 : FDIM * HID);
    float acc = (s < 32) ? b1[h] : 0.0f;
#pragma unroll
    for (int f = 0; f < FDIM; f++)
        acc = fmaf(xr[nl][f], W[f * HID + h], acc);
    if (s < 32) g_A[node * HID + h] = acc;
    else        g_B[node * HID + h] = acc;
}

// ======================= dense all-pairs: mma.sync fp16, f16x2 feature gen =======================
// smem u32 layout:
//   sW    [8][32][8]        = 2048 u32
//   sXJ16 [128][34] (pad)   = 4352 u32
//   sXI16 [32][34]  (pad)   = 1088 u32
//   sA    [32][32] f32      = 1024 u32
#define SW_OFF   0
#define SXJ_OFF  2048
#define SXI_OFF  (2048 + 4352)
#define SA_OFF   (2048 + 4352 + 1088)
#define DENSE_SMEM_U (2048 + 4352 + 1088 + 1024)
#define XJP 34
#define XIP 34

// pack two f32 -> f16x2 (lo in lower half)
__device__ __forceinline__ uint32_t pack_h2(float lo, float hi) {
    uint32_t r;
    asm("cvt.rn.f16x2.f32 %0, %1, %2;" : "=r"(r) : "f"(hi), "f"(lo));
    return r;
}
__device__ __forceinline__ uint32_t hsub2(uint32_t a, uint32_t b) {
    uint32_t r;
    asm("sub.f16x2 %0, %1, %2;" : "=r"(r) : "r"(a), "r"(b));
    return r;
}
__device__ __forceinline__ uint32_t habs2(uint32_t a) {
    return a & 0x7FFF7FFFu;
}
__device__ __forceinline__ uint32_t hmul2(uint32_t a, uint32_t b) {
    uint32_t r;
    asm("mul.f16x2 %0, %1, %2;" : "=r"(r) : "r"(a), "r"(b));
    return r;
}

__device__ __forceinline__ void mma_f16(float* D, uint32_t a0, uint32_t a1,
                                        uint32_t a2, uint32_t a3,
                                        uint32_t b0, uint32_t b1) {
    asm volatile(
        "mma.sync.aligned.m16n8k16.row.col.f32.f16.f16.f32 "
        "{%0,%1,%2,%3}, {%4,%5,%6,%7}, {%8,%9}, {%0,%1,%2,%3};"
        : "+f"(D[0]), "+f"(D[1]), "+f"(D[2]), "+f"(D[3])
        : "r"(a0), "r"(a1), "r"(a2), "r"(a3), "r"(b0), "r"(b1));
}

// fast sigmoid (MUFU) for dense P -- tolerance-safe
__device__ __forceinline__ float sigmoid_fast(float v) {
    return __fdividef(1.0f, 1.0f + __expf(-v));
}

__global__ __launch_bounds__(256, 2)
void dense_mma_kernel(const float* __restrict__ x,
                      const float* __restrict__ W1,
                      const float* __restrict__ W2,
                      const float* __restrict__ b2,
                      float* __restrict__ P) {
    extern __shared__ uint32_t smu[];
    uint32_t* sW    = smu + SW_OFF;      // [8 steps][32 lanes][8]
    uint32_t* sXJ16 = smu + SXJ_OFF;     // [128][34] f16x2 (feat pair per u32)
    uint32_t* sXI16 = smu + SXI_OFF;     // [32][34]
    float*    sA    = (float*)(smu + SA_OFF);  // [32][32]

    int t  = threadIdx.x;
    int i0 = blockIdx.x * BI;
    int j0 = blockIdx.y * BJ;

    // ---- stage xj block as f16x2 ----
    for (int k = t; k < BJ * 16; k += 256) {      // 16 float4 per row
        int row = k >> 4, c4 = k & 15;
        float4 v = __ldg((const float4*)(x + (j0 + row) * FDIM) + c4);
        sXJ16[row * XJP + c4 * 2]     = pack_h2(v.x, v.y);
        sXJ16[row * XJP + c4 * 2 + 1] = pack_h2(v.z, v.w);
    }
    // ---- stage xi block as f16x2 ----
    for (int k = t; k < BI * 16; k += 256) {
        int row = k >> 4, c4 = k & 15;
        float4 v = __ldg((const float4*)(x + (i0 + row) * FDIM) + c4);
        sXI16[row * XIP + c4 * 2]     = pack_h2(v.x, v.y);
        sXI16[row * XIP + c4 * 2 + 1] = pack_h2(v.z, v.w);
    }
    // ---- stage A_i ----
    for (int k = t; k < BI * HID; k += 256)
        sA[k] = g_A[(i0 + (k >> 5)) * HID + (k & 31)];
    // ---- prepack B fragments (W1 rows 128..255 -> f16x2, per-lane layout) ----
    for (int g = t; g < 8 * 32; g += 256) {
        int s = g >> 5, ln = g & 31;
        int qq = ln & 3, rr = ln >> 2;
        uint32_t* dst = sW + (s * 32 + ln) * 8;
        int kb = s * 16;
#pragma unroll
        for (int nt = 0; nt < 4; nt++) {
            int n = nt * 8 + rr;
            int f0 = kb + 2 * qq;
            int f2 = kb + 2 * qq + 8;
            float w00 = W1[(128 + f0) * HID + n];
            float w01 = W1[(128 + f0 + 1) * HID + n];
            float w20 = W1[(128 + f2) * HID + n];
            float w21 = W1[(128 + f2 + 1) * HID + n];
            dst[nt]     = pack_h2(w00, w01);
            dst[4 + nt] = pack_h2(w20, w21);
        }
    }
    __syncthreads();

    int lane = t & 31, wid = t >> 5;
    int q = lane & 3, r = lane >> 2;
    int jr0 = wid * 16 + r;        // D rows 0..7  -> j index
    int jr1 = jr0 + 8;             // D rows 8..15 -> j index

    // ---- hoist all B fragments to registers: 8 steps x 8 u32 = 64 regs ----
    uint32_t bf[8][8];
#pragma unroll
    for (int s = 0; s < 8; s++) {
        const uint32_t* bp = sW + (s * 32 + lane) * 8;
        float4 v0 = *(const float4*)bp;
        float4 v1 = *(const float4*)(bp + 4);
        bf[s][0] = __float_as_uint(v0.x); bf[s][1] = __float_as_uint(v0.y);
        bf[s][2] = __float_as_uint(v0.z); bf[s][3] = __float_as_uint(v0.w);
        bf[s][4] = __float_as_uint(v1.x); bf[s][5] = __float_as_uint(v1.y);
        bf[s][6] = __float_as_uint(v1.z); bf[s][7] = __float_as_uint(v1.w);
    }

    // ---- xj register cache (f16x2) ----
    uint32_t xjA0[4], xjB0[4], xjA1[4], xjB1[4];
#pragma unroll
    for (int u = 0; u < 4; u++) {
        xjA0[u] = sXJ16[jr0 * XJP + u * 8 + q];
        xjB0[u] = sXJ16[jr0 * XJP + u * 8 + q + 4];
        xjA1[u] = sXJ16[jr1 * XJP + u * 8 + q];
        xjB1[u] = sXJ16[jr1 * XJP + u * 8 + q + 4];
    }

    // epilogue constants
    float bj0[8], bj1[8], w2l[8];
#pragma unroll
    for (int nt = 0; nt < 4; nt++) {
        int h = nt * 8 + 2 * q;
        bj0[2 * nt]     = g_B[(j0 + jr0) * HID + h];
        bj0[2 * nt + 1] = g_B[(j0 + jr0) * HID + h + 1];
        bj1[2 * nt]     = g_B[(j0 + jr1) * HID + h];
        bj1[2 * nt + 1] = g_B[(j0 + jr1) * HID + h + 1];
        w2l[2 * nt]     = __ldg(W2 + h);
        w2l[2 * nt + 1] = __ldg(W2 + h + 1);
    }
    float b2v = __ldg(b2);

    for (int ii = 0; ii < BI; ii++) {
        uint32_t xiA[4], xiB[4];
#pragma unroll
        for (int u = 0; u < 4; u++) {
            xiA[u] = sXI16[ii * XIP + u * 8 + q];        // broadcast within quad
            xiB[u] = sXI16[ii * XIP + u * 8 + q + 4];
        }

        float D[16];
#pragma unroll
        for (int z = 0; z < 16; z++) D[z] = 0.0f;

#pragma unroll
        for (int s = 0; s < 8; s++) {
            int u = s & 3;
            uint32_t a0, a1, a2, a3;
            if (s < 4) {   // |xi - xj| block (K 0..63)
                a0 = habs2(hsub2(xiA[u], xjA0[u]));
                a1 = habs2(hsub2(xiA[u], xjA1[u]));
                a2 = habs2(hsub2(xiB[u], xjB0[u]));
                a3 = habs2(hsub2(xiB[u], xjB1[u]));
            } else {       // xi * xj block (K 64..127)
                a0 = hmul2(xiA[u], xjA0[u]);
                a1 = hmul2(xiA[u], xjA1[u]);
                a2 = hmul2(xiB[u], xjB0[u]);
                a3 = hmul2(xiB[u], xjB1[u]);
            }
            mma_f16(D + 0,  a0, a1, a2, a3, bf[s][0], bf[s][4]);
            mma_f16(D + 4,  a0, a1, a2, a3, bf[s][1], bf[s][5]);
            mma_f16(D + 8,  a0, a1, a2, a3, bf[s][2], bf[s][6]);
            mma_f16(D + 12, a0, a1, a2, a3, bf[s][3], bf[s][7]);
        }

        // ---- epilogue: add per-node terms, ReLU, W2 dot, quad reduce ----
        float p0 = 0.0f, p1 = 0.0f;
#pragma unroll
        for (int nt = 0; nt < 4; nt++) {
            float2 aiv = *(const float2*)(sA + ii * HID + nt * 8 + 2 * q);
            p0 += fmaxf(D[nt * 4 + 0] + aiv.x + bj0[2 * nt],     0.0f) * w2l[2 * nt];
            p0 += fmaxf(D[nt * 4 + 1] + aiv.y + bj0[2 * nt + 1], 0.0f) * w2l[2 * nt + 1];
            p1 += fmaxf(D[nt * 4 + 2] + aiv.x + bj1[2 * nt],     0.0f) * w2l[2 * nt];
            p1 += fmaxf(D[nt * 4 + 3] + aiv.y + bj1[2 * nt + 1], 0.0f) * w2l[2 * nt + 1];
        }
        p0 += __shfl_xor_sync(0xFFFFFFFF, p0, 1);
        p0 += __shfl_xor_sync(0xFFFFFFFF, p0, 2);
        p1 += __shfl_xor_sync(0xFFFFFFFF, p1, 1);
        p1 += __shfl_xor_sync(0xFFFFFFFF, p1, 2);
        if (q == 0) {
            P[(i0 + ii) * NODES + j0 + jr0] = sigmoid_fast(p0 + b2v);
            P[(i0 + ii) * NODES + j0 + jr1] = sigmoid_fast(p1 + b2v);
        }
    }
}

// ======================= sparse edge branch (fp32, exact) =======================
__device__ __forceinline__ unsigned long long pack2(float lo, float hi) {
    unsigned long long r;
    asm("mov.b64 %0, {%1, %2};" : "=l"(r) : "f"(lo), "f"(hi));
    return r;
}
__device__ __forceinline__ void unpack2(unsigned long long v, float& lo, float& hi) {
    asm("mov.b64 {%0, %1}, %2;" : "=f"(lo), "=f"(hi) : "l"(v));
}
__device__ __forceinline__ unsigned long long ffma2(unsigned long long a,
                                                    unsigned long long b,
                                                    unsigned long long c) {
    unsigned long long d;
    asm("fma.rn.f32x2 %0, %1, %2, %3;" : "=l"(d) : "l"(a), "l"(b), "l"(c));
    return d;
}

__global__ __launch_bounds__(256)
void edge_kernel(const float* __restrict__ x,
                 const int* __restrict__ ei,   // int32 (JAX x64 disabled)
                 const float* __restrict__ W1,
                 const float* __restrict__ W2,
                 const float* __restrict__ b2,
                 float* __restrict__ probs,
                 float* __restrict__ acts) {
    __shared__ unsigned long long s_Wc[FDIM][HH];
    __shared__ unsigned long long s_Wd[FDIM][HH];
    __shared__ float s_W2[HID];
    int t = threadIdx.x;
    for (int k = t; k < FDIM * HH; k += 256) {
        int f = k >> 4, hh = k & 15;
        float2 c = ((const float2*)(W1 + (128 + f) * HID))[hh];
        float2 d = ((const float2*)(W1 + (192 + f) * HID))[hh];
        s_Wc[f][hh] = pack2(c.x, c.y);
        s_Wd[f][hh] = pack2(d.x, d.y);
    }
    if (t < HID) s_W2[t] = W2[t];
    __syncthreads();

    int e = blockIdx.x * 256 + t;
    int s = ei[e];
    int d = ei[EDGES + e];

    unsigned long long acc[HH];
    {
        const float* Ar = g_A + s * HID;
        const float* Br = g_B + d * HID;
#pragma unroll
        for (int hh = 0; hh < HH; hh++)
            acc[hh] = pack2(Ar[2 * hh] + Br[2 * hh], Ar[2 * hh + 1] + Br[2 * hh + 1]);
    }

    const float4* xs4 = (const float4*)(x + s * FDIM);
    const float4* xd4 = (const float4*)(x + d * FDIM);
#pragma unroll 4
    for (int c = 0; c < FDIM / 4; c++) {
        float4 a = __ldg(xs4 + c);
        float4 b = __ldg(xd4 + c);
        float av[4] = {a.x, a.y, a.z, a.w};
        float bv[4] = {b.x, b.y, b.z, b.w};
#pragma unroll
        for (int u = 0; u < 4; u++) {
            int f = c * 4 + u;
            float ad = fabsf(av[u] - bv[u]);
            float pr = av[u] * bv[u];
            unsigned long long dd = pack2(ad, ad);
            unsigned long long pm = pack2(pr, pr);
#pragma unroll
            for (int hh = 0; hh < HH; hh++) {
                acc[hh] = ffma2(dd, s_Wc[f][hh], acc[hh]);
                acc[hh] = ffma2(pm, s_Wd[f][hh], acc[hh]);
            }
        }
    }

    float logit = b2[0];
#pragma unroll
    for (int hh = 0; hh < HH; hh++) {
        float lo, hi;
        unpack2(acc[hh], lo, hi);
        logit += fmaxf(lo, 0.0f) * s_W2[2 * hh] + fmaxf(hi, 0.0f) * s_W2[2 * hh + 1];
    }
    float prob = 1.0f / (1.0f + expf(-logit));   // exact path: acts threshold safety
    probs[e] = prob;
    acts[e]  = (prob > 0.4f) ? 1.0f : 0.0f;
}

// ======================= launch: prep -> {edge || dense} fork-join =======================
extern "C" void kernel_launch(void* const* d_in, const int* in_sizes, int n_in,
                              void* d_out, int out_size) {
    const float* x  = (const float*)d_in[0];
    const int*   ei = (const int*)d_in[1];     // int32 (JAX x64 disabled)
    const float* W1 = (const float*)d_in[3];
    const float* b1 = (const float*)d_in[4];
    const float* W2 = (const float*)d_in[5];
    const float* b2 = (const float*)d_in[6];

    float* out   = (float*)d_out;
    float* probs = out;
    float* acts  = out + EDGES;
    float* P     = out + 2 * EDGES;

    static cudaStream_t s2 = nullptr;
    static cudaEvent_t ev_fork = nullptr, ev_join = nullptr;
    if (s2 == nullptr) {
        cudaFuncSetAttribute(dense_mma_kernel,
                             cudaFuncAttributeMaxDynamicSharedMemorySize,
                             DENSE_SMEM_U * 4);
        cudaStreamCreateWithFlags(&s2, cudaStreamNonBlocking);
        cudaEventCreateWithFlags(&ev_fork, cudaEventDisableTiming);
        cudaEventCreateWithFlags(&ev_join, cudaEventDisableTiming);
    }

    // prep on the launch (default) stream
    prep_kernel<<<NODES / 4, 256>>>(x, W1, b1);

    // fork: edge branch runs on s2, concurrent with dense on the default stream
    cudaEventRecord(ev_fork, 0);
    cudaStreamWaitEvent(s2, ev_fork, 0);
    edge_kernel<<<EDGES / 256, 256, 0, s2>>>(x, ei, W1, W2, b2, probs, acts);
    cudaEventRecord(ev_join, s2);

    dim3 grid(NODES / BI, NODES / BJ);
    dense_mma_kernel<<<grid, 256, DENSE_SMEM_U * 4>>>(x, W1, W2, b2, P);

    // join: default stream waits for edge completion
    cudaStreamWaitEvent(0, ev_join, 0);
}